// round 8
// baseline (speedup 1.0000x reference)
#include <cuda_runtime.h>
#include <stdint.h>

// Problem constants
#define BATCH 4096
#define FEAT  4096
#define NP    16
#define DDIM  256
#define MROWS (BATCH * NP)   // 65536
#define EPS   1e-5f
#define INV_SCALE 0.0625f    // 1/sqrt(256)
#define QPRE   0.09017131f   // INV_SCALE * log2(e)

// ---------------- device scratch ----------------
#define RCHUNKS 32
__device__ float g_psum[RCHUNKS * FEAT];
__device__ float g_psumsq[RCHUNKS * FEAT];
__device__ float g_scale[FEAT];
__device__ float g_shift[FEAT];
__device__ float g_q[(size_t)MROWS * DDIM];
__device__ float g_k[(size_t)MROWS * DDIM];
__device__ float g_v[(size_t)MROWS * DDIM];

// bf16 2-way split of a fp32 pair: (hi_pair, lo_pair); lower half = y0.
__device__ __forceinline__ uint2 bfsplit2(float y0, float y1) {
    uint32_t hi;
    asm("cvt.rn.bf16x2.f32 %0, %1, %2;" : "=r"(hi) : "f"(y1), "f"(y0));
    float h0 = __uint_as_float(hi << 16);
    float h1 = __uint_as_float(hi & 0xffff0000u);
    uint32_t lo;
    asm("cvt.rn.bf16x2.f32 %0, %1, %2;" : "=r"(lo) : "f"(y1 - h1), "f"(y0 - h0));
    return make_uint2(hi, lo);
}
__device__ __forceinline__ uint32_t bfpack(float y0, float y1) {
    uint32_t h;
    asm("cvt.rn.bf16x2.f32 %0, %1, %2;" : "=r"(h) : "f"(y1), "f"(y0));
    return h;
}
__device__ __forceinline__ float ex2(float x) {
    float r;
    asm("ex2.approx.f32 %0, %1;" : "=f"(r) : "f"(x));
    return r;
}

#define MMA_BF16(c, a0, a1, a2, a3, b0, b1)                                \
    asm volatile(                                                          \
        "mma.sync.aligned.m16n8k16.row.col.f32.bf16.bf16.f32 "             \
        "{%0,%1,%2,%3}, {%4,%5,%6,%7}, {%8,%9}, {%0,%1,%2,%3};"            \
        : "+f"((c)[0]), "+f"((c)[1]), "+f"((c)[2]), "+f"((c)[3])           \
        : "r"(a0), "r"(a1), "r"(a2), "r"(a3), "r"(b0), "r"(b1))

// ---------------- BN pass 1 ----------------
__global__ void bn_pass1(const float* __restrict__ x) {
    int col = blockIdx.x * 256 + threadIdx.x;
    int r0  = blockIdx.y * (BATCH / RCHUNKS);
    float s = 0.f, ss = 0.f;
    #pragma unroll 4
    for (int r = 0; r < BATCH / RCHUNKS; r++) {
        float v = x[(size_t)(r0 + r) * FEAT + col];
        s += v; ss += v * v;
    }
    g_psum[blockIdx.y * FEAT + col]   = s;
    g_psumsq[blockIdx.y * FEAT + col] = ss;
}

// ---------------- BN pass 2 ----------------
__global__ void bn_pass2(const float* __restrict__ gamma,
                         const float* __restrict__ beta) {
    int col = blockIdx.x * blockDim.x + threadIdx.x;
    float s = 0.f, ss = 0.f;
    #pragma unroll
    for (int c = 0; c < RCHUNKS; c++) {
        s  += g_psum[c * FEAT + col];
        ss += g_psumsq[c * FEAT + col];
    }
    float mean = s * (1.f / BATCH);
    float var  = ss * (1.f / BATCH) - mean * mean;
    float rstd = rsqrtf(var + EPS);
    float a = rstd * gamma[col];
    g_scale[col] = a;
    g_shift[col] = beta[col] - mean * a;
}

// ---------------- bf16-split QKV GEMM, occupancy-2 version ----------------
// grid (3, 2, 512): w = weight, n0 = by*128, m0 = bz*128.
// 256 threads = 8 warps in 2(m) x 4(n); warp tile m64 x n32. acc = 64 regs.
#define PA   12
#define STG_U2 (128 * PA)                 // one A or B stage
#define SMEM_GEMM (4 * STG_U2 * 8)        // 49152 bytes (A0,A1,B0,B1)

__global__ void __launch_bounds__(256, 2) gemm_mma(
    const float* __restrict__ x,
    const float* __restrict__ wq, const float* __restrict__ wk,
    const float* __restrict__ wv,
    const float* __restrict__ bq, const float* __restrict__ bk_,
    const float* __restrict__ bv)
{
    extern __shared__ uint2 sm[];          // [A0 A1 B0 B1]
    const int tid = threadIdx.x;
    const int w   = blockIdx.x;
    const int n0  = blockIdx.y * 128;
    const int m0  = blockIdx.z * 128;

    const float* W    = (w == 0) ? wq : (w == 1) ? wk : wv;
    const float* bias = (w == 0) ? bq : (w == 1) ? bk_ : bv;
    float*       out  = (w == 0) ? g_q : (w == 1) ? g_k : g_v;

    const int lane = tid & 31, wid = tid >> 5;
    const int wm = wid >> 2;               // 0..1
    const int wn = wid & 3;                // 0..3
    const int g4 = lane >> 2, l4 = lane & 3;

    const int row = tid >> 1;              // 0..127 (A row and B row)
    const int akc = (tid & 1) * 8;         // k element offset
    const int apb = (tid & 1) * 4;         // k pair offset
    const float* asrc = x + (size_t)(m0 + row) * DDIM;
    const float* bsrc = W + (size_t)(n0 + row) * DDIM;
    const int fcb = (row & 15) * 256;      // BN feature col base

    float acc[4][4][4];
    #pragma unroll
    for (int tm = 0; tm < 4; tm++)
        #pragma unroll
        for (int nt = 0; nt < 4; nt++)
            #pragma unroll
            for (int i = 0; i < 4; i++) acc[tm][nt][i] = 0.f;

    float4 pa0, pa1, pb0, pb1;

    auto LDG = [&](int c) {
        int kabs = c * 16 + akc;
        pa0 = *(const float4*)(asrc + kabs);
        pa1 = *(const float4*)(asrc + kabs + 4);
        pb0 = *(const float4*)(bsrc + kabs);
        pb1 = *(const float4*)(bsrc + kabs + 4);
    };

    auto CVT_STS = [&](int c, int st) {
        int kabs = c * 16 + akc;
        const float4 sc0 = *(const float4*)(g_scale + fcb + kabs);
        const float4 sc1 = *(const float4*)(g_scale + fcb + kabs + 4);
        const float4 sh0 = *(const float4*)(g_shift + fcb + kabs);
        const float4 sh1 = *(const float4*)(g_shift + fcb + kabs + 4);
        uint2* adst = sm + (size_t)st * STG_U2 + row * PA + apb;
        adst[0] = bfsplit2(fmaf(pa0.x, sc0.x, sh0.x), fmaf(pa0.y, sc0.y, sh0.y));
        adst[1] = bfsplit2(fmaf(pa0.z, sc0.z, sh0.z), fmaf(pa0.w, sc0.w, sh0.w));
        adst[2] = bfsplit2(fmaf(pa1.x, sc1.x, sh1.x), fmaf(pa1.y, sc1.y, sh1.y));
        adst[3] = bfsplit2(fmaf(pa1.z, sc1.z, sh1.z), fmaf(pa1.w, sc1.w, sh1.w));
        uint2* bdst = sm + (2 + st) * STG_U2 + row * PA + apb;
        bdst[0] = bfsplit2(pb0.x, pb0.y);
        bdst[1] = bfsplit2(pb0.z, pb0.w);
        bdst[2] = bfsplit2(pb1.x, pb1.y);
        bdst[3] = bfsplit2(pb1.z, pb1.w);
    };

    auto MMA_CHUNK = [&](int st) {
        const uint2* A0 = sm + (size_t)st * STG_U2 + (wm * 64) * PA;
        const uint2* B0 = sm + (2 + st) * STG_U2 + (wn * 32) * PA;
        uint2 af[4][4];
        #pragma unroll
        for (int tm = 0; tm < 4; tm++) {
            int r = tm * 16 + g4;
            af[tm][0] = A0[r * PA + l4];
            af[tm][1] = A0[(r + 8) * PA + l4];
            af[tm][2] = A0[r * PA + l4 + 4];
            af[tm][3] = A0[(r + 8) * PA + l4 + 4];
        }
        uint2 fb0[4], fb1[4];
        #pragma unroll
        for (int nt = 0; nt < 4; nt++) {
            fb0[nt] = B0[(nt * 8 + g4) * PA + l4];
            fb1[nt] = B0[(nt * 8 + g4) * PA + l4 + 4];
        }
        // term-major: 16 independent accumulators per sweep
        #pragma unroll
        for (int nt = 0; nt < 4; nt++)
            #pragma unroll
            for (int tm = 0; tm < 4; tm++)
                MMA_BF16(acc[tm][nt], af[tm][0].x, af[tm][1].x,
                         af[tm][2].x, af[tm][3].x, fb0[nt].x, fb1[nt].x);
        #pragma unroll
        for (int nt = 0; nt < 4; nt++)
            #pragma unroll
            for (int tm = 0; tm < 4; tm++)
                MMA_BF16(acc[tm][nt], af[tm][0].x, af[tm][1].x,
                         af[tm][2].x, af[tm][3].x, fb0[nt].y, fb1[nt].y);
        #pragma unroll
        for (int nt = 0; nt < 4; nt++)
            #pragma unroll
            for (int tm = 0; tm < 4; tm++)
                MMA_BF16(acc[tm][nt], af[tm][0].y, af[tm][1].y,
                         af[tm][2].y, af[tm][3].y, fb0[nt].x, fb1[nt].x);
    };

    LDG(0);
    CVT_STS(0, 0);
    __syncthreads();
    #pragma unroll 1
    for (int c = 0; c < 16; c++) {
        if (c < 15) LDG(c + 1);
        MMA_CHUNK(c & 1);
        if (c < 15) {
            CVT_STS(c + 1, (c + 1) & 1);
            __syncthreads();
        }
    }

    const int rbase = m0 + wm * 64;
    const int cbase = n0 + wn * 32;
    #pragma unroll
    for (int tm = 0; tm < 4; tm++) {
        int r = rbase + tm * 16 + g4;
        #pragma unroll
        for (int nt = 0; nt < 4; nt++) {
            int col = cbase + nt * 8 + l4 * 2;
            float2 bb = *(const float2*)(bias + col);
            *(float2*)(out + (size_t)r * DDIM + col) =
                make_float2(acc[tm][nt][0] + bb.x, acc[tm][nt][1] + bb.y);
            *(float2*)(out + (size_t)(r + 8) * DDIM + col) =
                make_float2(acc[tm][nt][2] + bb.x, acc[tm][nt][3] + bb.y);
        }
    }
}

// ---------------- tensor-core attention, 128-thr CTA, 2 CTAs/batch --------
#define APITCH 12
#define VPITCH 132
// Qt: 128 rows (this CTA's e-half); Kt: 256 rows; Vh: 16 x VPITCH
#define SMEM_ATTN (128 * APITCH * 8 + 256 * APITCH * 8 + 16 * VPITCH * 4)

__global__ void __launch_bounds__(128) attn_tc(const float* __restrict__ x,
                                               float* __restrict__ out)
{
    extern __shared__ uint2 smq[];
    uint2* Qt = smq;                           // [128 e][p-pair] (hi,lo)
    uint2* Kt = smq + 128 * APITCH;            // [256 f][p-pair]
    uint32_t* Vh = (uint32_t*)(smq + (128 + 256) * APITCH);

    const int b    = blockIdx.x;
    const int half = blockIdx.y;               // which 128 e-rows
    const int tid  = threadIdx.x;
    const int lane = tid & 31, wid = tid >> 5; // wid 0..3
    const int g4 = lane >> 2, l4 = lane & 3;

    // ---- Q (this half only): transpose + split + pre-scale ----
    {
        const int j  = tid & 7;                // p-pair
        const int e0 = (tid >> 3) * 8;         // local e base (0..120)
        const float* q0p = g_q + (size_t)b * 4096 + (2 * j) * 256 + half * 128 + e0;
        float4 qa = *(const float4*)q0p;
        float4 qb = *(const float4*)(q0p + 4);
        float4 qc = *(const float4*)(q0p + 256);
        float4 qd = *(const float4*)(q0p + 260);
        float q0[8] = {qa.x, qa.y, qa.z, qa.w, qb.x, qb.y, qb.z, qb.w};
        float q1[8] = {qc.x, qc.y, qc.z, qc.w, qd.x, qd.y, qd.z, qd.w};
        #pragma unroll
        for (int i = 0; i < 8; i++)
            Qt[(e0 + i) * APITCH + j] = bfsplit2(q0[i] * QPRE, q1[i] * QPRE);
        // ---- K (full 256 f): two passes ----
        #pragma unroll
        for (int r = 0; r < 2; r++) {
            int f0 = r * 128 + e0;
            const float* k0p = g_k + (size_t)b * 4096 + (2 * j) * 256 + f0;
            float4 ka = *(const float4*)k0p;
            float4 kb = *(const float4*)(k0p + 4);
            float4 kc = *(const float4*)(k0p + 256);
            float4 kd = *(const float4*)(k0p + 260);
            float k0[8] = {ka.x, ka.y, ka.z, ka.w, kb.x, kb.y, kb.z, kb.w};
            float k1[8] = {kc.x, kc.y, kc.z, kc.w, kd.x, kd.y, kd.z, kd.w};
            #pragma unroll
            for (int i = 0; i < 8; i++)
                Kt[(f0 + i) * APITCH + j] = bfsplit2(k0[i], k1[i]);
        }
    }
    // ---- V: [p][f-pair] hi only ----
    {
        const int p  = tid >> 3;               // 0..15
        const int fq = (tid & 7) * 32;         // f base, 32 f per thread
        const float* vp = g_v + (size_t)b * 4096 + p * 256 + fq;
        #pragma unroll
        for (int h = 0; h < 4; h++) {
            float4 v0 = *(const float4*)(vp + h * 8);
            float4 v1 = *(const float4*)(vp + h * 8 + 4);
            uint32_t* d = Vh + p * VPITCH + (fq >> 1) + h * 4;
            d[0] = bfpack(v0.x, v0.y);
            d[1] = bfpack(v0.z, v0.w);
            d[2] = bfpack(v1.x, v1.y);
            d[3] = bfpack(v1.z, v1.w);
        }
    }
    __syncthreads();

    // ---- persistent Q fragments (local e index) ----
    uint2 af[2][4];
    #pragma unroll
    for (int tm = 0; tm < 2; tm++) {
        int eb = wid * 32 + tm * 16;
        af[tm][0] = Qt[(eb + g4) * APITCH + l4];
        af[tm][1] = Qt[(eb + g4 + 8) * APITCH + l4];
        af[tm][2] = Qt[(eb + g4) * APITCH + l4 + 4];
        af[tm][3] = Qt[(eb + g4 + 8) * APITCH + l4 + 4];
    }

    float av[2][2][4];
    #pragma unroll
    for (int tm = 0; tm < 2; tm++)
        #pragma unroll
        for (int np = 0; np < 2; np++)
            #pragma unroll
            for (int i = 0; i < 4; i++) av[tm][np][i] = 0.f;
    float srow[2][2] = {{0.f, 0.f}, {0.f, 0.f}};

    #pragma unroll
    for (int fc = 0; fc < 256; fc += 64) {
        float E[2][8][4];
        #pragma unroll
        for (int ng = 0; ng < 2; ng++) {
            uint2 kb0[4], kb1[4];
            #pragma unroll
            for (int j = 0; j < 4; j++) {
                int f = fc + (ng * 4 + j) * 8 + g4;
                kb0[j] = Kt[f * APITCH + l4];
                kb1[j] = Kt[f * APITCH + l4 + 4];
            }
            #pragma unroll
            for (int j = 0; j < 4; j++)
                #pragma unroll
                for (int tm = 0; tm < 2; tm++) {
                    float* c = E[tm][ng * 4 + j];
                    c[0] = c[1] = c[2] = c[3] = 0.f;
                }
            #pragma unroll
            for (int j = 0; j < 4; j++)
                #pragma unroll
                for (int tm = 0; tm < 2; tm++)
                    MMA_BF16(E[tm][ng * 4 + j], af[tm][0].x, af[tm][1].x,
                             af[tm][2].x, af[tm][3].x, kb0[j].x, kb1[j].x);
            #pragma unroll
            for (int j = 0; j < 4; j++)
                #pragma unroll
                for (int tm = 0; tm < 2; tm++)
                    MMA_BF16(E[tm][ng * 4 + j], af[tm][0].x, af[tm][1].x,
                             af[tm][2].x, af[tm][3].x, kb0[j].y, kb1[j].y);
            #pragma unroll
            for (int j = 0; j < 4; j++)
                #pragma unroll
                for (int tm = 0; tm < 2; tm++)
                    MMA_BF16(E[tm][ng * 4 + j], af[tm][0].y, af[tm][1].y,
                             af[tm][2].y, af[tm][3].y, kb0[j].x, kb1[j].x);
        }
        // ---- exp2 + row sums ----
        #pragma unroll
        for (int tm = 0; tm < 2; tm++)
            #pragma unroll
            for (int nt = 0; nt < 8; nt++) {
                float* c = E[tm][nt];
                c[0] = ex2(c[0]);
                c[1] = ex2(c[1]);
                c[2] = ex2(c[2]);
                c[3] = ex2(c[3]);
                srow[tm][0] += c[0] + c[1];
                srow[tm][1] += c[2] + c[3];
            }
        // ---- AV: P(bf16 hi) x V_hi ----
        #pragma unroll
        for (int s = 0; s < 4; s++) {
            uint32_t vb0[2], vb1[2];
            #pragma unroll
            for (int np = 0; np < 2; np++) {
                const uint32_t* vr = Vh + (np * 8 + g4) * VPITCH + (fc >> 1) + s * 8;
                vb0[np] = vr[l4];
                vb1[np] = vr[l4 + 4];
            }
            #pragma unroll
            for (int tm = 0; tm < 2; tm++) {
                uint32_t a0 = bfpack(E[tm][2 * s][0], E[tm][2 * s][1]);
                uint32_t a1 = bfpack(E[tm][2 * s][2], E[tm][2 * s][3]);
                uint32_t a2 = bfpack(E[tm][2 * s + 1][0], E[tm][2 * s + 1][1]);
                uint32_t a3 = bfpack(E[tm][2 * s + 1][2], E[tm][2 * s + 1][3]);
                #pragma unroll
                for (int np = 0; np < 2; np++)
                    MMA_BF16(av[tm][np], a0, a1, a2, a3, vb0[np], vb1[np]);
            }
        }
    }

    // ---- epilogue ----
    #pragma unroll
    for (int tm = 0; tm < 2; tm++) {
        float s0 = srow[tm][0];
        s0 += __shfl_xor_sync(0xffffffffu, s0, 1);
        s0 += __shfl_xor_sync(0xffffffffu, s0, 2);
        float s1 = srow[tm][1];
        s1 += __shfl_xor_sync(0xffffffffu, s1, 1);
        s1 += __shfl_xor_sync(0xffffffffu, s1, 2);
        float inv0 = 1.f / s0, inv1 = 1.f / s1;
        int e_lo = half * 128 + wid * 32 + tm * 16 + g4;
        #pragma unroll
        for (int np = 0; np < 2; np++) {
            int p = np * 8 + l4 * 2;
            size_t lo = (size_t)b * FEAT + e_lo * 16 + p;
            size_t hi = lo + 8 * 16;
            float2 x0 = *(const float2*)(x + lo);
            float2 x1 = *(const float2*)(x + hi);
            *(float2*)(out + lo) = make_float2(av[tm][np][0] * inv0 + x0.x,
                                               av[tm][np][1] * inv0 + x0.y);
            *(float2*)(out + hi) = make_float2(av[tm][np][2] * inv1 + x1.x,
                                               av[tm][np][3] * inv1 + x1.y);
        }
    }
}

// ---------------- launcher ----------------
extern "C" void kernel_launch(void* const* d_in, const int* in_sizes, int n_in,
                              void* d_out, int out_size) {
    const float* x     = (const float*)d_in[0];
    const float* WQ_w  = (const float*)d_in[1];
    const float* WQ_b  = (const float*)d_in[2];
    const float* WK_w  = (const float*)d_in[3];
    const float* WK_b  = (const float*)d_in[4];
    const float* WV_w  = (const float*)d_in[5];
    const float* WV_b  = (const float*)d_in[6];
    const float* gamma = (const float*)d_in[7];
    const float* beta  = (const float*)d_in[8];
    float* out = (float*)d_out;

    cudaFuncSetAttribute(gemm_mma, cudaFuncAttributeMaxDynamicSharedMemorySize,
                         SMEM_GEMM);
    cudaFuncSetAttribute(attn_tc, cudaFuncAttributeMaxDynamicSharedMemorySize,
                         SMEM_ATTN);

    bn_pass1<<<dim3(FEAT / 256, RCHUNKS), 256>>>(x);
    bn_pass2<<<FEAT / 256, 256>>>(gamma, beta);
    gemm_mma<<<dim3(3, 2, 512), 256, SMEM_GEMM>>>(x, WQ_w, WK_w, WV_w,
                                                  WQ_b, WK_b, WV_b);
    attn_tc<<<dim3(BATCH, 2), 128, SMEM_ATTN>>>(x, out);
}

// round 9
// speedup vs baseline: 1.9921x; 1.9921x over previous
#include <cuda_runtime.h>
#include <stdint.h>

// Problem constants
#define BATCH 4096
#define FEAT  4096
#define NP    16
#define DDIM  256
#define MROWS (BATCH * NP)   // 65536
#define EPS   1e-5f
#define INV_SCALE 0.0625f    // 1/sqrt(256)
#define QPRE   0.09017131f   // INV_SCALE * log2(e)

// ---------------- device scratch ----------------
#define RCHUNKS 32
__device__ float g_psum[RCHUNKS * FEAT];
__device__ float g_psumsq[RCHUNKS * FEAT];
__device__ float g_scale[FEAT];
__device__ float g_shift[FEAT];
__device__ float g_q[(size_t)MROWS * DDIM];
__device__ float g_k[(size_t)MROWS * DDIM];
__device__ float g_v[(size_t)MROWS * DDIM];

// fp16x2 pack: lower half = y0, upper half = y1
__device__ __forceinline__ uint32_t hpack(float y0, float y1) {
    uint32_t h;
    asm("cvt.rn.f16x2.f32 %0, %1, %2;" : "=r"(h) : "f"(y1), "f"(y0));
    return h;
}
__device__ __forceinline__ float ex2(float x) {
    float r;
    asm("ex2.approx.f32 %0, %1;" : "=f"(r) : "f"(x));
    return r;
}

#define MMA_FP16(c, a0, a1, a2, a3, b0, b1)                                \
    asm volatile(                                                          \
        "mma.sync.aligned.m16n8k16.row.col.f32.f16.f16.f32 "               \
        "{%0,%1,%2,%3}, {%4,%5,%6,%7}, {%8,%9}, {%0,%1,%2,%3};"            \
        : "+f"((c)[0]), "+f"((c)[1]), "+f"((c)[2]), "+f"((c)[3])           \
        : "r"(a0), "r"(a1), "r"(a2), "r"(a3), "r"(b0), "r"(b1))

// ---------------- BN pass 1 ----------------
__global__ void bn_pass1(const float* __restrict__ x) {
    int col = blockIdx.x * 256 + threadIdx.x;
    int r0  = blockIdx.y * (BATCH / RCHUNKS);
    float s = 0.f, ss = 0.f;
    #pragma unroll 4
    for (int r = 0; r < BATCH / RCHUNKS; r++) {
        float v = x[(size_t)(r0 + r) * FEAT + col];
        s += v; ss += v * v;
    }
    g_psum[blockIdx.y * FEAT + col]   = s;
    g_psumsq[blockIdx.y * FEAT + col] = ss;
}

// ---------------- BN pass 2 ----------------
__global__ void bn_pass2(const float* __restrict__ gamma,
                         const float* __restrict__ beta) {
    int col = blockIdx.x * blockDim.x + threadIdx.x;
    float s = 0.f, ss = 0.f;
    #pragma unroll
    for (int c = 0; c < RCHUNKS; c++) {
        s  += g_psum[c * FEAT + col];
        ss += g_psumsq[c * FEAT + col];
    }
    float mean = s * (1.f / BATCH);
    float var  = ss * (1.f / BATCH) - mean * mean;
    float rstd = rsqrtf(var + EPS);
    float a = rstd * gamma[col];
    g_scale[col] = a;
    g_shift[col] = beta[col] - mean * a;
}

// ---------------- single-term fp16 QKV GEMM, BN fused on A -----------------
// grid (3, 512): w = weight, m0 = by*128. 256 thr = 8 warps, warp tile m64xn64.
// K in 16 chunks of 16 (one fp16 mma k-step), double-buffered smem.
#define PG   12                            // uint32 pitch per row
#define A_U  (128 * PG)
#define B_U  (256 * PG)
#define SMEM_GEMM ((2 * A_U + 2 * B_U) * 4)   // 36864 bytes

__global__ void __launch_bounds__(256, 1) gemm_mma(
    const float* __restrict__ x,
    const float* __restrict__ wq, const float* __restrict__ wk,
    const float* __restrict__ wv,
    const float* __restrict__ bq, const float* __restrict__ bk_,
    const float* __restrict__ bv)
{
    extern __shared__ uint32_t smu[];      // [A0 A1 B0 B1]
    const int tid = threadIdx.x;
    const int w   = blockIdx.x;
    const int m0  = blockIdx.y * 128;

    const float* W    = (w == 0) ? wq : (w == 1) ? wk : wv;
    const float* bias = (w == 0) ? bq : (w == 1) ? bk_ : bv;
    float*       out  = (w == 0) ? g_q : (w == 1) ? g_k : g_v;

    const int lane = tid & 31, wid = tid >> 5;
    const int wm = wid >> 2;               // 0..1
    const int wn = wid & 3;                // 0..3
    const int g4 = lane >> 2, l4 = lane & 3;

    const int arow = tid >> 1;             // 0..127
    const int akc  = (tid & 1) * 8;        // A k element offset
    const int apu  = (tid & 1) * 4;        // A uint (pair) offset
    const int brow = tid;                  // 0..255
    const float* asrc = x + (size_t)(m0 + arow) * DDIM;
    const float* bsrc = W + (size_t)brow * DDIM;
    const int fcb = (arow & 15) * 256;     // BN feature col base

    float acc[4][8][4];
    #pragma unroll
    for (int tm = 0; tm < 4; tm++)
        #pragma unroll
        for (int nt = 0; nt < 8; nt++)
            #pragma unroll
            for (int i = 0; i < 4; i++) acc[tm][nt][i] = 0.f;

    float4 pa0, pa1, pb0, pb1, pb2, pb3;

    auto LDG = [&](int c) {
        int kabs = c * 16;
        pa0 = *(const float4*)(asrc + kabs + akc);
        pa1 = *(const float4*)(asrc + kabs + akc + 4);
        pb0 = *(const float4*)(bsrc + kabs);
        pb1 = *(const float4*)(bsrc + kabs + 4);
        pb2 = *(const float4*)(bsrc + kabs + 8);
        pb3 = *(const float4*)(bsrc + kabs + 12);
    };

    auto CVT_STS = [&](int c, int st) {
        int kabs = c * 16 + akc;
        const float4 sc0 = *(const float4*)(g_scale + fcb + kabs);
        const float4 sc1 = *(const float4*)(g_scale + fcb + kabs + 4);
        const float4 sh0 = *(const float4*)(g_shift + fcb + kabs);
        const float4 sh1 = *(const float4*)(g_shift + fcb + kabs + 4);
        uint32_t* adst = smu + (size_t)st * A_U + arow * PG + apu;
        adst[0] = hpack(fmaf(pa0.x, sc0.x, sh0.x), fmaf(pa0.y, sc0.y, sh0.y));
        adst[1] = hpack(fmaf(pa0.z, sc0.z, sh0.z), fmaf(pa0.w, sc0.w, sh0.w));
        adst[2] = hpack(fmaf(pa1.x, sc1.x, sh1.x), fmaf(pa1.y, sc1.y, sh1.y));
        adst[3] = hpack(fmaf(pa1.z, sc1.z, sh1.z), fmaf(pa1.w, sc1.w, sh1.w));
        uint32_t* bdst = smu + 2 * A_U + (size_t)st * B_U + brow * PG;
        bdst[0] = hpack(pb0.x, pb0.y);
        bdst[1] = hpack(pb0.z, pb0.w);
        bdst[2] = hpack(pb1.x, pb1.y);
        bdst[3] = hpack(pb1.z, pb1.w);
        bdst[4] = hpack(pb2.x, pb2.y);
        bdst[5] = hpack(pb2.z, pb2.w);
        bdst[6] = hpack(pb3.x, pb3.y);
        bdst[7] = hpack(pb3.z, pb3.w);
    };

    auto MMA_CHUNK = [&](int st) {
        const uint32_t* A0 = smu + (size_t)st * A_U + (wm * 64) * PG;
        const uint32_t* B0 = smu + 2 * A_U + (size_t)st * B_U + (wn * 64) * PG;
        uint32_t af[4][4];
        #pragma unroll
        for (int tm = 0; tm < 4; tm++) {
            int r = tm * 16 + g4;
            af[tm][0] = A0[r * PG + l4];
            af[tm][1] = A0[(r + 8) * PG + l4];
            af[tm][2] = A0[r * PG + l4 + 4];
            af[tm][3] = A0[(r + 8) * PG + l4 + 4];
        }
        #pragma unroll
        for (int nt = 0; nt < 8; nt++) {
            uint32_t fb0 = B0[(nt * 8 + g4) * PG + l4];
            uint32_t fb1 = B0[(nt * 8 + g4) * PG + l4 + 4];
            #pragma unroll
            for (int tm = 0; tm < 4; tm++)
                MMA_FP16(acc[tm][nt], af[tm][0], af[tm][1],
                         af[tm][2], af[tm][3], fb0, fb1);
        }
    };

    LDG(0);
    CVT_STS(0, 0);
    __syncthreads();
    #pragma unroll 1
    for (int c = 0; c < 16; c++) {
        if (c < 15) LDG(c + 1);
        MMA_CHUNK(c & 1);
        if (c < 15) {
            CVT_STS(c + 1, (c + 1) & 1);
            __syncthreads();
        }
    }

    const int rbase = m0 + wm * 64;
    const int cbase = wn * 64;
    #pragma unroll
    for (int tm = 0; tm < 4; tm++) {
        int r = rbase + tm * 16 + g4;
        #pragma unroll
        for (int nt = 0; nt < 8; nt++) {
            int col = cbase + nt * 8 + l4 * 2;
            float2 bb = *(const float2*)(bias + col);
            *(float2*)(out + (size_t)r * DDIM + col) =
                make_float2(acc[tm][nt][0] + bb.x, acc[tm][nt][1] + bb.y);
            *(float2*)(out + (size_t)(r + 8) * DDIM + col) =
                make_float2(acc[tm][nt][2] + bb.x, acc[tm][nt][3] + bb.y);
        }
    }
}

// ---------------- fp16 tensor-core attention, 128-thr CTA, 2/batch --------
#define APITCH 12                          // uint32 per row (Qt/Kt)
#define VPITCH 132                         // uint32 per row (Vh)
#define SMEM_ATTN ((128 + 256) * APITCH * 4 + 16 * VPITCH * 4)   // 26880 B

__global__ void __launch_bounds__(128) attn_tc(const float* __restrict__ x,
                                               float* __restrict__ out)
{
    extern __shared__ uint32_t smq[];
    uint32_t* Qt = smq;                    // [128 e][p-pair] fp16x2, pre-scaled
    uint32_t* Kt = smq + 128 * APITCH;     // [256 f][p-pair]
    uint32_t* Vh = smq + (128 + 256) * APITCH;   // [16 p][f-pair]

    const int b    = blockIdx.x;
    const int half = blockIdx.y;
    const int tid  = threadIdx.x;
    const int lane = tid & 31, wid = tid >> 5;   // wid 0..3
    const int g4 = lane >> 2, l4 = lane & 3;

    // ---- Q (this half): transpose + pack + pre-scale; K full ----
    {
        const int j  = tid & 7;                 // p-pair
        const int e0 = (tid >> 3) * 8;          // local e base
        const float* q0p = g_q + (size_t)b * 4096 + (2 * j) * 256 + half * 128 + e0;
        float4 qa = *(const float4*)q0p;
        float4 qb = *(const float4*)(q0p + 4);
        float4 qc = *(const float4*)(q0p + 256);
        float4 qd = *(const float4*)(q0p + 260);
        float q0[8] = {qa.x, qa.y, qa.z, qa.w, qb.x, qb.y, qb.z, qb.w};
        float q1[8] = {qc.x, qc.y, qc.z, qc.w, qd.x, qd.y, qd.z, qd.w};
        #pragma unroll
        for (int i = 0; i < 8; i++)
            Qt[(e0 + i) * APITCH + j] = hpack(q0[i] * QPRE, q1[i] * QPRE);
        #pragma unroll
        for (int r = 0; r < 2; r++) {
            int f0 = r * 128 + e0;
            const float* k0p = g_k + (size_t)b * 4096 + (2 * j) * 256 + f0;
            float4 ka = *(const float4*)k0p;
            float4 kb = *(const float4*)(k0p + 4);
            float4 kc = *(const float4*)(k0p + 256);
            float4 kd = *(const float4*)(k0p + 260);
            float k0[8] = {ka.x, ka.y, ka.z, ka.w, kb.x, kb.y, kb.z, kb.w};
            float k1[8] = {kc.x, kc.y, kc.z, kc.w, kd.x, kd.y, kd.z, kd.w};
            #pragma unroll
            for (int i = 0; i < 8; i++)
                Kt[(f0 + i) * APITCH + j] = hpack(k0[i], k1[i]);
        }
    }
    // ---- V: [p][f-pair] fp16 ----
    {
        const int p  = tid >> 3;
        const int fq = (tid & 7) * 32;
        const float* vp = g_v + (size_t)b * 4096 + p * 256 + fq;
        #pragma unroll
        for (int h = 0; h < 4; h++) {
            float4 v0 = *(const float4*)(vp + h * 8);
            float4 v1 = *(const float4*)(vp + h * 8 + 4);
            uint32_t* d = Vh + p * VPITCH + (fq >> 1) + h * 4;
            d[0] = hpack(v0.x, v0.y);
            d[1] = hpack(v0.z, v0.w);
            d[2] = hpack(v1.x, v1.y);
            d[3] = hpack(v1.z, v1.w);
        }
    }
    __syncthreads();

    // ---- persistent Q fragments ----
    uint32_t af[2][4];
    #pragma unroll
    for (int tm = 0; tm < 2; tm++) {
        int eb = wid * 32 + tm * 16;
        af[tm][0] = Qt[(eb + g4) * APITCH + l4];
        af[tm][1] = Qt[(eb + g4 + 8) * APITCH + l4];
        af[tm][2] = Qt[(eb + g4) * APITCH + l4 + 4];
        af[tm][3] = Qt[(eb + g4 + 8) * APITCH + l4 + 4];
    }

    float av[2][2][4];
    #pragma unroll
    for (int tm = 0; tm < 2; tm++)
        #pragma unroll
        for (int np = 0; np < 2; np++)
            #pragma unroll
            for (int i = 0; i < 4; i++) av[tm][np][i] = 0.f;
    float srow[2][2] = {{0.f, 0.f}, {0.f, 0.f}};

    #pragma unroll
    for (int fc = 0; fc < 256; fc += 64) {
        float E[2][8][4];
        // ---- S chunk: single fp16 term, 16 independent mmas ----
        #pragma unroll
        for (int nt = 0; nt < 8; nt++) {
            int f = fc + nt * 8 + g4;
            uint32_t kb0 = Kt[f * APITCH + l4];
            uint32_t kb1 = Kt[f * APITCH + l4 + 4];
            #pragma unroll
            for (int tm = 0; tm < 2; tm++) {
                float* c = E[tm][nt];
                c[0] = c[1] = c[2] = c[3] = 0.f;
                MMA_FP16(c, af[tm][0], af[tm][1], af[tm][2], af[tm][3],
                         kb0, kb1);
            }
        }
        // ---- exp2 + row sums ----
        #pragma unroll
        for (int tm = 0; tm < 2; tm++)
            #pragma unroll
            for (int nt = 0; nt < 8; nt++) {
                float* c = E[tm][nt];
                c[0] = ex2(c[0]);
                c[1] = ex2(c[1]);
                c[2] = ex2(c[2]);
                c[3] = ex2(c[3]);
                srow[tm][0] += c[0] + c[1];
                srow[tm][1] += c[2] + c[3];
            }
        // ---- AV: P(fp16) x V(fp16) ----
        #pragma unroll
        for (int s = 0; s < 4; s++) {
            uint32_t vb0[2], vb1[2];
            #pragma unroll
            for (int np = 0; np < 2; np++) {
                const uint32_t* vr = Vh + (np * 8 + g4) * VPITCH + (fc >> 1) + s * 8;
                vb0[np] = vr[l4];
                vb1[np] = vr[l4 + 4];
            }
            #pragma unroll
            for (int tm = 0; tm < 2; tm++) {
                uint32_t a0 = hpack(E[tm][2 * s][0], E[tm][2 * s][1]);
                uint32_t a1 = hpack(E[tm][2 * s][2], E[tm][2 * s][3]);
                uint32_t a2 = hpack(E[tm][2 * s + 1][0], E[tm][2 * s + 1][1]);
                uint32_t a3 = hpack(E[tm][2 * s + 1][2], E[tm][2 * s + 1][3]);
                #pragma unroll
                for (int np = 0; np < 2; np++)
                    MMA_FP16(av[tm][np], a0, a1, a2, a3, vb0[np], vb1[np]);
            }
        }
    }

    // ---- epilogue ----
    #pragma unroll
    for (int tm = 0; tm < 2; tm++) {
        float s0 = srow[tm][0];
        s0 += __shfl_xor_sync(0xffffffffu, s0, 1);
        s0 += __shfl_xor_sync(0xffffffffu, s0, 2);
        float s1 = srow[tm][1];
        s1 += __shfl_xor_sync(0xffffffffu, s1, 1);
        s1 += __shfl_xor_sync(0xffffffffu, s1, 2);
        float inv0 = 1.f / s0, inv1 = 1.f / s1;
        int e_lo = half * 128 + wid * 32 + tm * 16 + g4;
        #pragma unroll
        for (int np = 0; np < 2; np++) {
            int p = np * 8 + l4 * 2;
            size_t lo = (size_t)b * FEAT + e_lo * 16 + p;
            size_t hi = lo + 8 * 16;
            float2 x0 = *(const float2*)(x + lo);
            float2 x1 = *(const float2*)(x + hi);
            *(float2*)(out + lo) = make_float2(av[tm][np][0] * inv0 + x0.x,
                                               av[tm][np][1] * inv0 + x0.y);
            *(float2*)(out + hi) = make_float2(av[tm][np][2] * inv1 + x1.x,
                                               av[tm][np][3] * inv1 + x1.y);
        }
    }
}

// ---------------- launcher ----------------
extern "C" void kernel_launch(void* const* d_in, const int* in_sizes, int n_in,
                              void* d_out, int out_size) {
    const float* x     = (const float*)d_in[0];
    const float* WQ_w  = (const float*)d_in[1];
    const float* WQ_b  = (const float*)d_in[2];
    const float* WK_w  = (const float*)d_in[3];
    const float* WK_b  = (const float*)d_in[4];
    const float* WV_w  = (const float*)d_in[5];
    const float* WV_b  = (const float*)d_in[6];
    const float* gamma = (const float*)d_in[7];
    const float* beta  = (const float*)d_in[8];
    float* out = (float*)d_out;

    cudaFuncSetAttribute(gemm_mma, cudaFuncAttributeMaxDynamicSharedMemorySize,
                         SMEM_GEMM);
    cudaFuncSetAttribute(attn_tc, cudaFuncAttributeMaxDynamicSharedMemorySize,
                         SMEM_ATTN);

    bn_pass1<<<dim3(FEAT / 256, RCHUNKS), 256>>>(x);
    bn_pass2<<<FEAT / 256, 256>>>(gamma, beta);
    gemm_mma<<<dim3(3, 512), 256, SMEM_GEMM>>>(x, WQ_w, WK_w, WV_w,
                                               WQ_b, WK_b, WV_b);
    attn_tc<<<dim3(BATCH, 2), 128, SMEM_ATTN>>>(x, out);
}

// round 10
// speedup vs baseline: 3.2569x; 1.6349x over previous
#include <cuda_runtime.h>
#include <stdint.h>

// Problem constants
#define BATCH 4096
#define FEAT  4096
#define NP    16
#define DDIM  256
#define MROWS (BATCH * NP)   // 65536
#define EPS   1e-5f
#define QPRE   0.09017131f   // (1/sqrt(256)) * log2(e)

// ---------------- device scratch ----------------
#define RCHUNKS 32
__device__ float g_psum[RCHUNKS * FEAT];
__device__ float g_psumsq[RCHUNKS * FEAT];
__device__ float g_scale[FEAT];
__device__ float g_shift[FEAT];
__device__ uint32_t g_xnh[(size_t)MROWS * 128];  // BN(x) fp16x2, 32 MB
__device__ uint32_t g_wh[3 * 256 * 128];          // weights fp16x2 (WQ pre-scaled)
__device__ uint32_t g_qh[(size_t)MROWS * 128];    // Q' fp16x2
__device__ uint32_t g_kh[(size_t)MROWS * 128];
__device__ uint32_t g_vh[(size_t)MROWS * 128];

__device__ __forceinline__ uint32_t hpack(float y0, float y1) {
    uint32_t h;
    asm("cvt.rn.f16x2.f32 %0, %1, %2;" : "=r"(h) : "f"(y1), "f"(y0));
    return h;
}
__device__ __forceinline__ float ex2(float x) {
    float r;
    asm("ex2.approx.f32 %0, %1;" : "=f"(r) : "f"(x));
    return r;
}
__device__ __forceinline__ void cp16(uint32_t daddr, const void* src) {
    asm volatile("cp.async.cg.shared.global [%0], [%1], 16;"
                 :: "r"(daddr), "l"(src) : "memory");
}

#define MMA_FP16(c, a0, a1, a2, a3, b0, b1)                                \
    asm volatile(                                                          \
        "mma.sync.aligned.m16n8k16.row.col.f32.f16.f16.f32 "               \
        "{%0,%1,%2,%3}, {%4,%5,%6,%7}, {%8,%9}, {%0,%1,%2,%3};"            \
        : "+f"((c)[0]), "+f"((c)[1]), "+f"((c)[2]), "+f"((c)[3])           \
        : "r"(a0), "r"(a1), "r"(a2), "r"(a3), "r"(b0), "r"(b1))

// ---------------- BN pass 1 ----------------
__global__ void bn_pass1(const float* __restrict__ x) {
    int col = blockIdx.x * 256 + threadIdx.x;
    int r0  = blockIdx.y * (BATCH / RCHUNKS);
    float s = 0.f, ss = 0.f;
    #pragma unroll 4
    for (int r = 0; r < BATCH / RCHUNKS; r++) {
        float v = x[(size_t)(r0 + r) * FEAT + col];
        s += v; ss += v * v;
    }
    g_psum[blockIdx.y * FEAT + col]   = s;
    g_psumsq[blockIdx.y * FEAT + col] = ss;
}

// ---------------- BN pass 2 ----------------
__global__ void bn_pass2(const float* __restrict__ gamma,
                         const float* __restrict__ beta) {
    int col = blockIdx.x * blockDim.x + threadIdx.x;
    float s = 0.f, ss = 0.f;
    #pragma unroll
    for (int c = 0; c < RCHUNKS; c++) {
        s  += g_psum[c * FEAT + col];
        ss += g_psumsq[c * FEAT + col];
    }
    float mean = s * (1.f / BATCH);
    float var  = ss * (1.f / BATCH) - mean * mean;
    float rstd = rsqrtf(var + EPS);
    float a = rstd * gamma[col];
    g_scale[col] = a;
    g_shift[col] = beta[col] - mean * a;
}

// ---------------- xn -> fp16 (BN fused) ----------------
__global__ void xn_fp16(const float* __restrict__ x) {
    int i = blockIdx.x * 256 + threadIdx.x;
    size_t e = (size_t)i * 8;
    int col = (int)(e & 4095);
    float4 v0 = *(const float4*)(x + e);
    float4 v1 = *(const float4*)(x + e + 4);
    float4 sc0 = *(const float4*)(g_scale + col);
    float4 sc1 = *(const float4*)(g_scale + col + 4);
    float4 sh0 = *(const float4*)(g_shift + col);
    float4 sh1 = *(const float4*)(g_shift + col + 4);
    uint4 o;
    o.x = hpack(fmaf(v0.x, sc0.x, sh0.x), fmaf(v0.y, sc0.y, sh0.y));
    o.y = hpack(fmaf(v0.z, sc0.z, sh0.z), fmaf(v0.w, sc0.w, sh0.w));
    o.z = hpack(fmaf(v1.x, sc1.x, sh1.x), fmaf(v1.y, sc1.y, sh1.y));
    o.w = hpack(fmaf(v1.z, sc1.z, sh1.z), fmaf(v1.w, sc1.w, sh1.w));
    *(uint4*)(g_xnh + e / 2) = o;
}

// ---------------- W -> fp16 (WQ scaled by QPRE) ----------------
__global__ void w_fp16(const float* __restrict__ wq,
                       const float* __restrict__ wk,
                       const float* __restrict__ wv) {
    int i = blockIdx.x * 256 + threadIdx.x;    // pair index, 3*32768 total
    int w = i >> 15;
    int idx = i & 32767;
    const float* src = (w == 0) ? wq : (w == 1) ? wk : wv;
    float2 v = ((const float2*)src)[idx];
    float s = (w == 0) ? QPRE : 1.f;
    g_wh[i] = hpack(v.x * s, v.y * s);
}

// ---------------- fp16 cp.async QKV GEMM ----------------
// grid (3, 512). 256 thr = 8 warps (2m x 4n), warp tile m64 x n64.
// BK=32 (8 chunks), 4-stage cp.async ring.
#define GP    20                          // uint32 pitch per row
#define A_STG (128 * GP)
#define B_STG (256 * GP)
#define NSTG  4
#define SMEM_GEMM ((A_STG + B_STG) * NSTG * 4)   // 122880 bytes

__global__ void __launch_bounds__(256, 1) gemm_mma(
    const float* __restrict__ bq, const float* __restrict__ bk_,
    const float* __restrict__ bv)
{
    extern __shared__ uint32_t smu[];
    const int tid = threadIdx.x;
    const int w   = blockIdx.x;
    const int m0  = blockIdx.y * 128;

    const float* bias = (w == 0) ? bq : (w == 1) ? bk_ : bv;
    uint32_t*    outp = (w == 0) ? g_qh : (w == 1) ? g_kh : g_vh;
    const float  bs   = (w == 0) ? QPRE : 1.f;

    const int lane = tid & 31, wid = tid >> 5;
    const int wm = wid >> 2, wn = wid & 3;
    const int g4 = lane >> 2, l4 = lane & 3;

    const uint32_t* asrc = g_xnh + (size_t)m0 * 128;
    const uint32_t* bsrc = g_wh + w * 32768;
    uint32_t sbase = (uint32_t)__cvta_generic_to_shared(smu);

    const int arow = tid >> 2, aseg = tid & 3;   // also used for B

    auto ISSUE = [&](int c, int st) {
        // A: 128 rows x 64B (4 segs) = 512 cp16; 2 per thread
        #pragma unroll
        for (int t = 0; t < 2; t++) {
            int i = tid + t * 256;
            int row = i >> 2, seg = i & 3;
            cp16(sbase + (st * A_STG + row * GP + seg * 4) * 4,
                 asrc + (size_t)row * 128 + c * 16 + seg * 4);
        }
        // B: 256 rows x 64B = 1024 cp16; 4 per thread
        #pragma unroll
        for (int t = 0; t < 4; t++) {
            int i = tid + t * 256;
            int row = i >> 2, seg = i & 3;
            cp16(sbase + (NSTG * A_STG + st * B_STG + row * GP + seg * 4) * 4,
                 bsrc + (size_t)row * 128 + c * 16 + seg * 4);
        }
        asm volatile("cp.async.commit_group;" ::: "memory");
    };

    float acc[4][8][4];
    #pragma unroll
    for (int tm = 0; tm < 4; tm++)
        #pragma unroll
        for (int nt = 0; nt < 8; nt++)
            #pragma unroll
            for (int i = 0; i < 4; i++) acc[tm][nt][i] = 0.f;

    ISSUE(0, 0); ISSUE(1, 1); ISSUE(2, 2);

    #pragma unroll 1
    for (int c = 0; c < 8; c++) {
        if (c < 6) {
            asm volatile("cp.async.wait_group 2;" ::: "memory");
        } else {
            asm volatile("cp.async.wait_group 0;" ::: "memory");
        }
        __syncthreads();
        const int st = c & 3;
        const uint32_t* A0 = smu + st * A_STG + (wm * 64) * GP;
        const uint32_t* B0 = smu + NSTG * A_STG + st * B_STG + (wn * 64) * GP;
        #pragma unroll
        for (int kk = 0; kk < 2; kk++) {
            uint32_t af[4][4];
            #pragma unroll
            for (int tm = 0; tm < 4; tm++) {
                int r = tm * 16 + g4;
                af[tm][0] = A0[r * GP + kk * 8 + l4];
                af[tm][1] = A0[(r + 8) * GP + kk * 8 + l4];
                af[tm][2] = A0[r * GP + kk * 8 + l4 + 4];
                af[tm][3] = A0[(r + 8) * GP + kk * 8 + l4 + 4];
            }
            #pragma unroll
            for (int nt = 0; nt < 8; nt++) {
                uint32_t fb0 = B0[(nt * 8 + g4) * GP + kk * 8 + l4];
                uint32_t fb1 = B0[(nt * 8 + g4) * GP + kk * 8 + l4 + 4];
                #pragma unroll
                for (int tm = 0; tm < 4; tm++)
                    MMA_FP16(acc[tm][nt], af[tm][0], af[tm][1],
                             af[tm][2], af[tm][3], fb0, fb1);
            }
        }
        __syncthreads();
        if (c < 5) ISSUE(c + 3, (c + 3) & 3);
    }

    // ---- epilogue: bias add (scaled), pack fp16, store ----
    const int rbase = m0 + wm * 64;
    const int cbase = wn * 64;
    #pragma unroll
    for (int tm = 0; tm < 4; tm++) {
        int r = rbase + tm * 16 + g4;
        #pragma unroll
        for (int nt = 0; nt < 8; nt++) {
            int col = cbase + nt * 8 + l4 * 2;
            float2 bb = *(const float2*)(bias + col);
            float bx = bb.x * bs, by = bb.y * bs;
            outp[(size_t)r * 128 + (col >> 1)] =
                hpack(acc[tm][nt][0] + bx, acc[tm][nt][1] + by);
            outp[(size_t)(r + 8) * 128 + (col >> 1)] =
                hpack(acc[tm][nt][2] + bx, acc[tm][nt][3] + by);
        }
    }
}

// ---------------- fp16 tensor-core attention, 128-thr CTA, 2/batch --------
#define APITCH 12
#define VPITCH 132
#define SMEM_ATTN ((128 + 256) * APITCH * 4 + 16 * VPITCH * 4)   // 26880 B

__global__ void __launch_bounds__(128) attn_tc(const float* __restrict__ x,
                                               float* __restrict__ out)
{
    extern __shared__ uint32_t smq[];
    uint32_t* Qt = smq;                    // [128 e][p-pair] fp16x2 (pre-scaled)
    uint32_t* Kt = smq + 128 * APITCH;     // [256 f][p-pair]
    uint32_t* Vh = smq + (128 + 256) * APITCH;   // [16 p][f-pair]

    const int b    = blockIdx.x;
    const int half = blockIdx.y;
    const int tid  = threadIdx.x;
    const int lane = tid & 31, wid = tid >> 5;
    const int g4 = lane >> 2, l4 = lane & 3;

    // ---- Q (this half) + K (full): load fp16 rows, transpose via prmt ----
    {
        const int j  = tid & 7;                 // p-pair
        const int e0 = (tid >> 3) * 8;          // local e base
        {
            const uint32_t* q0 = g_qh + ((size_t)b * 16 + 2 * j) * 128
                                 + half * 64 + (e0 >> 1);
            uint4 qa = *(const uint4*)q0;
            uint4 qb = *(const uint4*)(q0 + 128);
            uint32_t av[4] = {qa.x, qa.y, qa.z, qa.w};
            uint32_t bv4[4] = {qb.x, qb.y, qb.z, qb.w};
            #pragma unroll
            for (int i = 0; i < 4; i++) {
                Qt[(e0 + 2 * i) * APITCH + j]     = __byte_perm(av[i], bv4[i], 0x5410);
                Qt[(e0 + 2 * i + 1) * APITCH + j] = __byte_perm(av[i], bv4[i], 0x7632);
            }
        }
        #pragma unroll
        for (int r = 0; r < 2; r++) {
            int f0 = r * 128 + e0;
            const uint32_t* k0 = g_kh + ((size_t)b * 16 + 2 * j) * 128 + (f0 >> 1);
            uint4 ka = *(const uint4*)k0;
            uint4 kb = *(const uint4*)(k0 + 128);
            uint32_t av[4] = {ka.x, ka.y, ka.z, ka.w};
            uint32_t bv4[4] = {kb.x, kb.y, kb.z, kb.w};
            #pragma unroll
            for (int i = 0; i < 4; i++) {
                Kt[(f0 + 2 * i) * APITCH + j]     = __byte_perm(av[i], bv4[i], 0x5410);
                Kt[(f0 + 2 * i + 1) * APITCH + j] = __byte_perm(av[i], bv4[i], 0x7632);
            }
        }
    }
    // ---- V: direct fp16 copy [p][f-pair] ----
    {
        const int p  = tid >> 3;
        const int t8 = (tid & 7) * 16;          // uint offset within row
        const uint4* vsrc = (const uint4*)(g_vh + ((size_t)b * 16 + p) * 128 + t8);
        uint4* vdst = (uint4*)(Vh + p * VPITCH + t8);
        vdst[0] = vsrc[0];
        vdst[1] = vsrc[1];
        vdst[2] = vsrc[2];
        vdst[3] = vsrc[3];
    }
    __syncthreads();

    // ---- persistent Q fragments (already QPRE-scaled) ----
    uint32_t af[2][4];
    #pragma unroll
    for (int tm = 0; tm < 2; tm++) {
        int eb = wid * 32 + tm * 16;
        af[tm][0] = Qt[(eb + g4) * APITCH + l4];
        af[tm][1] = Qt[(eb + g4 + 8) * APITCH + l4];
        af[tm][2] = Qt[(eb + g4) * APITCH + l4 + 4];
        af[tm][3] = Qt[(eb + g4 + 8) * APITCH + l4 + 4];
    }

    float av[2][2][4];
    #pragma unroll
    for (int tm = 0; tm < 2; tm++)
        #pragma unroll
        for (int np = 0; np < 2; np++)
            #pragma unroll
            for (int i = 0; i < 4; i++) av[tm][np][i] = 0.f;
    float srow[2][2] = {{0.f, 0.f}, {0.f, 0.f}};

    #pragma unroll
    for (int fc = 0; fc < 256; fc += 64) {
        float E[2][8][4];
        #pragma unroll
        for (int nt = 0; nt < 8; nt++) {
            int f = fc + nt * 8 + g4;
            uint32_t kb0 = Kt[f * APITCH + l4];
            uint32_t kb1 = Kt[f * APITCH + l4 + 4];
            #pragma unroll
            for (int tm = 0; tm < 2; tm++) {
                float* c = E[tm][nt];
                c[0] = c[1] = c[2] = c[3] = 0.f;
                MMA_FP16(c, af[tm][0], af[tm][1], af[tm][2], af[tm][3],
                         kb0, kb1);
            }
        }
        #pragma unroll
        for (int tm = 0; tm < 2; tm++)
            #pragma unroll
            for (int nt = 0; nt < 8; nt++) {
                float* c = E[tm][nt];
                c[0] = ex2(c[0]);
                c[1] = ex2(c[1]);
                c[2] = ex2(c[2]);
                c[3] = ex2(c[3]);
                srow[tm][0] += c[0] + c[1];
                srow[tm][1] += c[2] + c[3];
            }
        #pragma unroll
        for (int s = 0; s < 4; s++) {
            uint32_t vb0[2], vb1[2];
            #pragma unroll
            for (int np = 0; np < 2; np++) {
                const uint32_t* vr = Vh + (np * 8 + g4) * VPITCH + (fc >> 1) + s * 8;
                vb0[np] = vr[l4];
                vb1[np] = vr[l4 + 4];
            }
            #pragma unroll
            for (int tm = 0; tm < 2; tm++) {
                uint32_t a0 = hpack(E[tm][2 * s][0], E[tm][2 * s][1]);
                uint32_t a1 = hpack(E[tm][2 * s][2], E[tm][2 * s][3]);
                uint32_t a2 = hpack(E[tm][2 * s + 1][0], E[tm][2 * s + 1][1]);
                uint32_t a3 = hpack(E[tm][2 * s + 1][2], E[tm][2 * s + 1][3]);
                #pragma unroll
                for (int np = 0; np < 2; np++)
                    MMA_FP16(av[tm][np], a0, a1, a2, a3, vb0[np], vb1[np]);
            }
        }
    }

    // ---- epilogue ----
    #pragma unroll
    for (int tm = 0; tm < 2; tm++) {
        float s0 = srow[tm][0];
        s0 += __shfl_xor_sync(0xffffffffu, s0, 1);
        s0 += __shfl_xor_sync(0xffffffffu, s0, 2);
        float s1 = srow[tm][1];
        s1 += __shfl_xor_sync(0xffffffffu, s1, 1);
        s1 += __shfl_xor_sync(0xffffffffu, s1, 2);
        float inv0 = 1.f / s0, inv1 = 1.f / s1;
        int e_lo = half * 128 + wid * 32 + tm * 16 + g4;
        #pragma unroll
        for (int np = 0; np < 2; np++) {
            int p = np * 8 + l4 * 2;
            size_t lo = (size_t)b * FEAT + e_lo * 16 + p;
            size_t hi = lo + 8 * 16;
            float2 x0 = *(const float2*)(x + lo);
            float2 x1 = *(const float2*)(x + hi);
            *(float2*)(out + lo) = make_float2(av[tm][np][0] * inv0 + x0.x,
                                               av[tm][np][1] * inv0 + x0.y);
            *(float2*)(out + hi) = make_float2(av[tm][np][2] * inv1 + x1.x,
                                               av[tm][np][3] * inv1 + x1.y);
        }
    }
}

// ---------------- launcher ----------------
extern "C" void kernel_launch(void* const* d_in, const int* in_sizes, int n_in,
                              void* d_out, int out_size) {
    const float* x     = (const float*)d_in[0];
    const float* WQ_w  = (const float*)d_in[1];
    const float* WQ_b  = (const float*)d_in[2];
    const float* WK_w  = (const float*)d_in[3];
    const float* WK_b  = (const float*)d_in[4];
    const float* WV_w  = (const float*)d_in[5];
    const float* WV_b  = (const float*)d_in[6];
    const float* gamma = (const float*)d_in[7];
    const float* beta  = (const float*)d_in[8];
    float* out = (float*)d_out;

    cudaFuncSetAttribute(gemm_mma, cudaFuncAttributeMaxDynamicSharedMemorySize,
                         SMEM_GEMM);
    cudaFuncSetAttribute(attn_tc, cudaFuncAttributeMaxDynamicSharedMemorySize,
                         SMEM_ATTN);

    bn_pass1<<<dim3(FEAT / 256, RCHUNKS), 256>>>(x);
    w_fp16<<<384, 256>>>(WQ_w, WK_w, WV_w);
    bn_pass2<<<FEAT / 256, 256>>>(gamma, beta);
    xn_fp16<<<(MROWS * 256 / 8) / 256, 256>>>(x);
    gemm_mma<<<dim3(3, 512), 256, SMEM_GEMM>>>(WQ_b, WK_b, WV_b);
    attn_tc<<<dim3(BATCH, 2), 128, SMEM_ATTN>>>(x, out);
}

// round 11
// speedup vs baseline: 3.3719x; 1.0353x over previous
#include <cuda_runtime.h>
#include <stdint.h>

// Problem constants
#define BATCH 4096
#define FEAT  4096
#define NP    16
#define DDIM  256
#define MROWS (BATCH * NP)   // 65536
#define EPS   1e-5f
#define QPRE   0.09017131f   // (1/sqrt(256)) * log2(e)

// ---------------- device scratch ----------------
#define RCHUNKS 64
__device__ float g_psum[RCHUNKS * FEAT];
__device__ float g_psumsq[RCHUNKS * FEAT];
__device__ float g_scale[FEAT];
__device__ float g_shift[FEAT];
__device__ uint32_t g_xnh[(size_t)MROWS * 128];  // BN(x) fp16x2, 32 MB
__device__ uint32_t g_wh[3 * 256 * 128];          // weights fp16x2 (WQ pre-scaled)
__device__ uint32_t g_qh[(size_t)MROWS * 128];    // Q' fp16x2
__device__ uint32_t g_kh[(size_t)MROWS * 128];
__device__ uint32_t g_vh[(size_t)MROWS * 128];

__device__ __forceinline__ uint32_t hpack(float y0, float y1) {
    uint32_t h;
    asm("cvt.rn.f16x2.f32 %0, %1, %2;" : "=r"(h) : "f"(y1), "f"(y0));
    return h;
}
__device__ __forceinline__ float ex2(float x) {
    float r;
    asm("ex2.approx.f32 %0, %1;" : "=f"(r) : "f"(x));
    return r;
}
__device__ __forceinline__ void cp16(uint32_t daddr, const void* src) {
    asm volatile("cp.async.cg.shared.global [%0], [%1], 16;"
                 :: "r"(daddr), "l"(src) : "memory");
}

#define MMA_FP16(c, a0, a1, a2, a3, b0, b1)                                \
    asm volatile(                                                          \
        "mma.sync.aligned.m16n8k16.row.col.f32.f16.f16.f32 "               \
        "{%0,%1,%2,%3}, {%4,%5,%6,%7}, {%8,%9}, {%0,%1,%2,%3};"            \
        : "+f"((c)[0]), "+f"((c)[1]), "+f"((c)[2]), "+f"((c)[3])           \
        : "r"(a0), "r"(a1), "r"(a2), "r"(a3), "r"(b0), "r"(b1))

// ---------------- BN pass 1 ----------------
__global__ void bn_pass1(const float* __restrict__ x) {
    int col = blockIdx.x * 256 + threadIdx.x;
    int r0  = blockIdx.y * (BATCH / RCHUNKS);
    float s = 0.f, ss = 0.f;
    #pragma unroll 4
    for (int r = 0; r < BATCH / RCHUNKS; r++) {
        float v = x[(size_t)(r0 + r) * FEAT + col];
        s += v; ss += v * v;
    }
    g_psum[blockIdx.y * FEAT + col]   = s;
    g_psumsq[blockIdx.y * FEAT + col] = ss;
}

// ---------------- BN pass 2 ----------------
__global__ void bn_pass2(const float* __restrict__ gamma,
                         const float* __restrict__ beta) {
    int col = blockIdx.x * blockDim.x + threadIdx.x;
    float s = 0.f, ss = 0.f;
    #pragma unroll
    for (int c = 0; c < RCHUNKS; c++) {
        s  += g_psum[c * FEAT + col];
        ss += g_psumsq[c * FEAT + col];
    }
    float mean = s * (1.f / BATCH);
    float var  = ss * (1.f / BATCH) - mean * mean;
    float rstd = rsqrtf(var + EPS);
    float a = rstd * gamma[col];
    g_scale[col] = a;
    g_shift[col] = beta[col] - mean * a;
}

// ---------------- xn -> fp16 (BN fused) ----------------
__global__ void xn_fp16(const float* __restrict__ x) {
    int i = blockIdx.x * 256 + threadIdx.x;
    size_t e = (size_t)i * 8;
    int col = (int)(e & 4095);
    float4 v0 = *(const float4*)(x + e);
    float4 v1 = *(const float4*)(x + e + 4);
    float4 sc0 = *(const float4*)(g_scale + col);
    float4 sc1 = *(const float4*)(g_scale + col + 4);
    float4 sh0 = *(const float4*)(g_shift + col);
    float4 sh1 = *(const float4*)(g_shift + col + 4);
    uint4 o;
    o.x = hpack(fmaf(v0.x, sc0.x, sh0.x), fmaf(v0.y, sc0.y, sh0.y));
    o.y = hpack(fmaf(v0.z, sc0.z, sh0.z), fmaf(v0.w, sc0.w, sh0.w));
    o.z = hpack(fmaf(v1.x, sc1.x, sh1.x), fmaf(v1.y, sc1.y, sh1.y));
    o.w = hpack(fmaf(v1.z, sc1.z, sh1.z), fmaf(v1.w, sc1.w, sh1.w));
    *(uint4*)(g_xnh + e / 2) = o;
}

// ---------------- W -> fp16 (WQ scaled by QPRE) ----------------
__global__ void w_fp16(const float* __restrict__ wq,
                       const float* __restrict__ wk,
                       const float* __restrict__ wv) {
    int i = blockIdx.x * 256 + threadIdx.x;    // pair index, 3*32768 total
    int w = i >> 15;
    int idx = i & 32767;
    const float* src = (w == 0) ? wq : (w == 1) ? wk : wv;
    float2 v = ((const float2*)src)[idx];
    float s = (w == 0) ? QPRE : 1.f;
    g_wh[i] = hpack(v.x * s, v.y * s);
}

// ---------------- fp16 cp.async QKV GEMM, 512 threads ----------------
// grid (3, 512). 512 thr = 16 warps (4m x 4n), warp tile m32 x n64.
// BK=32 (8 chunks), 4-stage cp.async ring.
#define GP    20                          // uint32 pitch per row
#define A_STG (128 * GP)
#define B_STG (256 * GP)
#define NSTG  4
#define SMEM_GEMM ((A_STG + B_STG) * NSTG * 4)   // 122880 bytes

__global__ void __launch_bounds__(512, 1) gemm_mma(
    const float* __restrict__ bq, const float* __restrict__ bk_,
    const float* __restrict__ bv)
{
    extern __shared__ uint32_t smu[];
    const int tid = threadIdx.x;
    const int w   = blockIdx.x;
    const int m0  = blockIdx.y * 128;

    const float* bias = (w == 0) ? bq : (w == 1) ? bk_ : bv;
    uint32_t*    outp = (w == 0) ? g_qh : (w == 1) ? g_kh : g_vh;
    const float  bs   = (w == 0) ? QPRE : 1.f;

    const int lane = tid & 31, wid = tid >> 5;
    const int wm = wid >> 2, wn = wid & 3;     // 4 x 4 warps
    const int g4 = lane >> 2, l4 = lane & 3;

    const uint32_t* asrc = g_xnh + (size_t)m0 * 128;
    const uint32_t* bsrc = g_wh + w * 32768;
    uint32_t sbase = (uint32_t)__cvta_generic_to_shared(smu);

    auto ISSUE = [&](int c, int st) {
        // A: 128 rows x 4 segs = 512 cp16; 1 per thread
        {
            int row = tid >> 2, seg = tid & 3;
            cp16(sbase + (st * A_STG + row * GP + seg * 4) * 4,
                 asrc + (size_t)row * 128 + c * 16 + seg * 4);
        }
        // B: 256 rows x 4 segs = 1024 cp16; 2 per thread
        #pragma unroll
        for (int t = 0; t < 2; t++) {
            int i = tid + t * 512;
            int row = i >> 2, seg = i & 3;
            cp16(sbase + (NSTG * A_STG + st * B_STG + row * GP + seg * 4) * 4,
                 bsrc + (size_t)row * 128 + c * 16 + seg * 4);
        }
        asm volatile("cp.async.commit_group;" ::: "memory");
    };

    float acc[2][8][4];
    #pragma unroll
    for (int tm = 0; tm < 2; tm++)
        #pragma unroll
        for (int nt = 0; nt < 8; nt++)
            #pragma unroll
            for (int i = 0; i < 4; i++) acc[tm][nt][i] = 0.f;

    ISSUE(0, 0); ISSUE(1, 1); ISSUE(2, 2);

    #pragma unroll 1
    for (int c = 0; c < 8; c++) {
        if (c < 6) {
            asm volatile("cp.async.wait_group 2;" ::: "memory");
        } else {
            asm volatile("cp.async.wait_group 0;" ::: "memory");
        }
        __syncthreads();
        const int st = c & 3;
        const uint32_t* A0 = smu + st * A_STG + (wm * 32) * GP;
        const uint32_t* B0 = smu + NSTG * A_STG + st * B_STG + (wn * 64) * GP;
        #pragma unroll
        for (int kk = 0; kk < 2; kk++) {
            uint32_t af[2][4];
            #pragma unroll
            for (int tm = 0; tm < 2; tm++) {
                int r = tm * 16 + g4;
                af[tm][0] = A0[r * GP + kk * 8 + l4];
                af[tm][1] = A0[(r + 8) * GP + kk * 8 + l4];
                af[tm][2] = A0[r * GP + kk * 8 + l4 + 4];
                af[tm][3] = A0[(r + 8) * GP + kk * 8 + l4 + 4];
            }
            #pragma unroll
            for (int nt = 0; nt < 8; nt++) {
                uint32_t fb0 = B0[(nt * 8 + g4) * GP + kk * 8 + l4];
                uint32_t fb1 = B0[(nt * 8 + g4) * GP + kk * 8 + l4 + 4];
                #pragma unroll
                for (int tm = 0; tm < 2; tm++)
                    MMA_FP16(acc[tm][nt], af[tm][0], af[tm][1],
                             af[tm][2], af[tm][3], fb0, fb1);
            }
        }
        __syncthreads();
        if (c < 5) ISSUE(c + 3, (c + 3) & 3);
    }

    // ---- epilogue: bias add (scaled), pack fp16, store ----
    const int rbase = m0 + wm * 32;
    const int cbase = wn * 64;
    #pragma unroll
    for (int tm = 0; tm < 2; tm++) {
        int r = rbase + tm * 16 + g4;
        #pragma unroll
        for (int nt = 0; nt < 8; nt++) {
            int col = cbase + nt * 8 + l4 * 2;
            float2 bb = *(const float2*)(bias + col);
            float bx = bb.x * bs, by = bb.y * bs;
            outp[(size_t)r * 128 + (col >> 1)] =
                hpack(acc[tm][nt][0] + bx, acc[tm][nt][1] + by);
            outp[(size_t)(r + 8) * 128 + (col >> 1)] =
                hpack(acc[tm][nt][2] + bx, acc[tm][nt][3] + by);
        }
    }
}

// ---------------- fp16 tensor-core attention, 128-thr CTA, 2/batch --------
// f-chunks of 32 (8 chunks) to shrink live registers -> higher occupancy.
#define APITCH 12
#define VPITCH 132
#define SMEM_ATTN ((128 + 256) * APITCH * 4 + 16 * VPITCH * 4)   // 26880 B

__global__ void __launch_bounds__(128) attn_tc(const float* __restrict__ x,
                                               float* __restrict__ out)
{
    extern __shared__ uint32_t smq[];
    uint32_t* Qt = smq;                    // [128 e][p-pair] fp16x2 (pre-scaled)
    uint32_t* Kt = smq + 128 * APITCH;     // [256 f][p-pair]
    uint32_t* Vh = smq + (128 + 256) * APITCH;   // [16 p][f-pair]

    const int b    = blockIdx.x;
    const int half = blockIdx.y;
    const int tid  = threadIdx.x;
    const int lane = tid & 31, wid = tid >> 5;
    const int g4 = lane >> 2, l4 = lane & 3;

    // ---- Q (this half) + K (full): load fp16 rows, transpose via prmt ----
    {
        const int j  = tid & 7;                 // p-pair
        const int e0 = (tid >> 3) * 8;          // local e base
        {
            const uint32_t* q0 = g_qh + ((size_t)b * 16 + 2 * j) * 128
                                 + half * 64 + (e0 >> 1);
            uint4 qa = *(const uint4*)q0;
            uint4 qb = *(const uint4*)(q0 + 128);
            uint32_t av4[4] = {qa.x, qa.y, qa.z, qa.w};
            uint32_t bv4[4] = {qb.x, qb.y, qb.z, qb.w};
            #pragma unroll
            for (int i = 0; i < 4; i++) {
                Qt[(e0 + 2 * i) * APITCH + j]     = __byte_perm(av4[i], bv4[i], 0x5410);
                Qt[(e0 + 2 * i + 1) * APITCH + j] = __byte_perm(av4[i], bv4[i], 0x7632);
            }
        }
        #pragma unroll
        for (int r = 0; r < 2; r++) {
            int f0 = r * 128 + e0;
            const uint32_t* k0 = g_kh + ((size_t)b * 16 + 2 * j) * 128 + (f0 >> 1);
            uint4 ka = *(const uint4*)k0;
            uint4 kb = *(const uint4*)(k0 + 128);
            uint32_t av4[4] = {ka.x, ka.y, ka.z, ka.w};
            uint32_t bv4[4] = {kb.x, kb.y, kb.z, kb.w};
            #pragma unroll
            for (int i = 0; i < 4; i++) {
                Kt[(f0 + 2 * i) * APITCH + j]     = __byte_perm(av4[i], bv4[i], 0x5410);
                Kt[(f0 + 2 * i + 1) * APITCH + j] = __byte_perm(av4[i], bv4[i], 0x7632);
            }
        }
    }
    // ---- V: direct fp16 copy [p][f-pair] ----
    {
        const int p  = tid >> 3;
        const int t8 = (tid & 7) * 16;
        const uint4* vsrc = (const uint4*)(g_vh + ((size_t)b * 16 + p) * 128 + t8);
        uint4* vdst = (uint4*)(Vh + p * VPITCH + t8);
        vdst[0] = vsrc[0];
        vdst[1] = vsrc[1];
        vdst[2] = vsrc[2];
        vdst[3] = vsrc[3];
    }
    __syncthreads();

    // ---- persistent Q fragments (already QPRE-scaled) ----
    uint32_t af[2][4];
    #pragma unroll
    for (int tm = 0; tm < 2; tm++) {
        int eb = wid * 32 + tm * 16;
        af[tm][0] = Qt[(eb + g4) * APITCH + l4];
        af[tm][1] = Qt[(eb + g4 + 8) * APITCH + l4];
        af[tm][2] = Qt[(eb + g4) * APITCH + l4 + 4];
        af[tm][3] = Qt[(eb + g4 + 8) * APITCH + l4 + 4];
    }

    float av[2][2][4];
    #pragma unroll
    for (int tm = 0; tm < 2; tm++)
        #pragma unroll
        for (int np = 0; np < 2; np++)
            #pragma unroll
            for (int i = 0; i < 4; i++) av[tm][np][i] = 0.f;
    float srow[2][2] = {{0.f, 0.f}, {0.f, 0.f}};

    #pragma unroll 1
    for (int fc = 0; fc < 256; fc += 32) {
        float E[2][4][4];
        // ---- S: 4 n-tiles x 2 m-tiles ----
        #pragma unroll
        for (int nt = 0; nt < 4; nt++) {
            int f = fc + nt * 8 + g4;
            uint32_t kb0 = Kt[f * APITCH + l4];
            uint32_t kb1 = Kt[f * APITCH + l4 + 4];
            #pragma unroll
            for (int tm = 0; tm < 2; tm++) {
                float* c = E[tm][nt];
                c[0] = c[1] = c[2] = c[3] = 0.f;
                MMA_FP16(c, af[tm][0], af[tm][1], af[tm][2], af[tm][3],
                         kb0, kb1);
            }
        }
        // ---- exp2 + row sums ----
        #pragma unroll
        for (int tm = 0; tm < 2; tm++)
            #pragma unroll
            for (int nt = 0; nt < 4; nt++) {
                float* c = E[tm][nt];
                c[0] = ex2(c[0]);
                c[1] = ex2(c[1]);
                c[2] = ex2(c[2]);
                c[3] = ex2(c[3]);
                srow[tm][0] += c[0] + c[1];
                srow[tm][1] += c[2] + c[3];
            }
        // ---- AV: P(fp16) x V(fp16) ----
        #pragma unroll
        for (int s = 0; s < 2; s++) {
            uint32_t vb0[2], vb1[2];
            #pragma unroll
            for (int np = 0; np < 2; np++) {
                const uint32_t* vr = Vh + (np * 8 + g4) * VPITCH + (fc >> 1) + s * 8;
                vb0[np] = vr[l4];
                vb1[np] = vr[l4 + 4];
            }
            #pragma unroll
            for (int tm = 0; tm < 2; tm++) {
                uint32_t a0 = hpack(E[tm][2 * s][0], E[tm][2 * s][1]);
                uint32_t a1 = hpack(E[tm][2 * s][2], E[tm][2 * s][3]);
                uint32_t a2 = hpack(E[tm][2 * s + 1][0], E[tm][2 * s + 1][1]);
                uint32_t a3 = hpack(E[tm][2 * s + 1][2], E[tm][2 * s + 1][3]);
                #pragma unroll
                for (int np = 0; np < 2; np++)
                    MMA_FP16(av[tm][np], a0, a1, a2, a3, vb0[np], vb1[np]);
            }
        }
    }

    // ---- epilogue ----
    #pragma unroll
    for (int tm = 0; tm < 2; tm++) {
        float s0 = srow[tm][0];
        s0 += __shfl_xor_sync(0xffffffffu, s0, 1);
        s0 += __shfl_xor_sync(0xffffffffu, s0, 2);
        float s1 = srow[tm][1];
        s1 += __shfl_xor_sync(0xffffffffu, s1, 1);
        s1 += __shfl_xor_sync(0xffffffffu, s1, 2);
        float inv0 = 1.f / s0, inv1 = 1.f / s1;
        int e_lo = half * 128 + wid * 32 + tm * 16 + g4;
        #pragma unroll
        for (int np = 0; np < 2; np++) {
            int p = np * 8 + l4 * 2;
            size_t lo = (size_t)b * FEAT + e_lo * 16 + p;
            size_t hi = lo + 8 * 16;
            float2 x0 = *(const float2*)(x + lo);
            float2 x1 = *(const float2*)(x + hi);
            *(float2*)(out + lo) = make_float2(av[tm][np][0] * inv0 + x0.x,
                                               av[tm][np][1] * inv0 + x0.y);
            *(float2*)(out + hi) = make_float2(av[tm][np][2] * inv1 + x1.x,
                                               av[tm][np][3] * inv1 + x1.y);
        }
    }
}

// ---------------- launcher ----------------
extern "C" void kernel_launch(void* const* d_in, const int* in_sizes, int n_in,
                              void* d_out, int out_size) {
    const float* x     = (const float*)d_in[0];
    const float* WQ_w  = (const float*)d_in[1];
    const float* WQ_b  = (const float*)d_in[2];
    const float* WK_w  = (const float*)d_in[3];
    const float* WK_b  = (const float*)d_in[4];
    const float* WV_w  = (const float*)d_in[5];
    const float* WV_b  = (const float*)d_in[6];
    const float* gamma = (const float*)d_in[7];
    const float* beta  = (const float*)d_in[8];
    float* out = (float*)d_out;

    cudaFuncSetAttribute(gemm_mma, cudaFuncAttributeMaxDynamicSharedMemorySize,
                         SMEM_GEMM);
    cudaFuncSetAttribute(attn_tc, cudaFuncAttributeMaxDynamicSharedMemorySize,
                         SMEM_ATTN);

    bn_pass1<<<dim3(FEAT / 256, RCHUNKS), 256>>>(x);
    w_fp16<<<384, 256>>>(WQ_w, WK_w, WV_w);
    bn_pass2<<<FEAT / 256, 256>>>(gamma, beta);
    xn_fp16<<<(MROWS * 256 / 8) / 256, 256>>>(x);
    gemm_mma<<<dim3(3, 512), 512, SMEM_GEMM>>>(WQ_b, WK_b, WV_b);
    attn_tc<<<dim3(BATCH, 2), 128, SMEM_ATTN>>>(x, out);
}